// round 14
// baseline (speedup 1.0000x reference)
#include <cuda_runtime.h>
#include <math.h>

#define FIN 512
#define HD  16
#define CD  7
#define NMAX 100000
#define EMAX 3200000
#define TPB  256

typedef unsigned long long u64;

// ---------------- scratch (static device globals) ----------------
__device__ int   g_cnt [NMAX];        // in-degree (w/o self-loop); re-zeroed by scan3
__device__ int   g_rows[NMAX + 1];    // CSR row starts (+ total at [n])
__device__ int   g_cur [NMAX];        // fill cursor
__device__ int   g_bsum[128];         // scan block sums
__device__ float g_dinv[NMAX];
__device__ int2  g_edge[EMAX];        // CSR: {src, bitcast(dinv[src])}
__device__ float g_h1  [NMAX * HD];
__device__ float g_h2  [NMAX * 8];    // 7 classes padded to 8 (col7 == 0)
__device__ int   g_abar;              // agg barrier arrive counter
__device__ volatile int g_aflag;      // agg barrier release flag
__device__ int   g_adone;             // agg exit counter (self-reset)

// ---------------- f32x2 helpers ----------------
__device__ __forceinline__ u64 pk2(float lo, float hi) {
    u64 r; asm("mov.b64 %0, {%1, %2};" : "=l"(r) : "f"(lo), "f"(hi)); return r;
}
__device__ __forceinline__ void upk2(float& lo, float& hi, u64 v) {
    asm("mov.b64 {%0, %1}, %2;" : "=f"(lo), "=f"(hi) : "l"(v));
}
__device__ __forceinline__ void fma2(u64& d, u64 a, u64 b) {
    asm("fma.rn.f32x2 %0, %1, %2, %0;" : "+l"(d) : "l"(a), "l"(b));
}

// ---------------- side stream / events (created before harness checkpoints) --
static cudaStream_t g_sideStream = 0;
static cudaEvent_t  g_evFork = 0, g_evJoin = 0;
namespace {
struct StreamInit {
    StreamInit() {
        int lo, hi;
        cudaDeviceGetStreamPriorityRange(&lo, &hi);
        cudaStreamCreateWithPriority(&g_sideStream, cudaStreamNonBlocking, hi);
        cudaEventCreateWithFlags(&g_evFork, cudaEventDisableTiming);
        cudaEventCreateWithFlags(&g_evJoin, cudaEventDisableTiming);
    }
};
StreamInit g_streamInit;
}

// ---------------- GEMM1: h1 = x @ W1, f32x2 packed over column pairs --------
// Same staging/tiling as the proven R1 kernel. Thread (ng=t>>1, jg=t&1) owns
// nodes {2ng, 2ng+1} x cols jg*8..+7. W float4 rows reinterpret as col-pair
// u64s (zero repacking); x lanes stride 66 words = 2 mod 32 -> conflict-free.

__global__ __launch_bounds__(256) void k_gemm1(const float* __restrict__ x,
                                               const float* __restrict__ W1, int n) {
    __shared__ float4 sW[32 * 4];        // 32 k x 16 j
    __shared__ float  sX[256 * 33];      // 256 nodes x 32 k (+1 pad)

    const int t  = threadIdx.x;
    const int n0 = blockIdx.x * 256;
    const int ng = t >> 1;               // 0..127 -> nodes 2ng, 2ng+1
    const int jg = t & 1;                // col group: cols jg*8..+7

    u64 acc[2][4];                       // [node][colpair]
#pragma unroll
    for (int p = 0; p < 2; p++)
#pragma unroll
        for (int c = 0; c < 4; c++) acc[p][c] = 0ull;

    for (int k0 = 0; k0 < FIN; k0 += 32) {
        __syncthreads();
        if (t < 128) {
            sW[t] = *(const float4*)(W1 + (size_t)(k0 + (t >> 2)) * HD + (t & 3) * 4);
        }
#pragma unroll
        for (int i = 0; i < 8; i++) {
            int f    = t + 256 * i;
            int nl   = f >> 3;
            int kq   = f & 7;
            int node = n0 + nl;
            float4 v = make_float4(0.f, 0.f, 0.f, 0.f);
            if (node < n) v = *(const float4*)(x + (size_t)node * FIN + k0 + kq * 4);
            float* sp = &sX[nl * 33 + kq * 4];
            sp[0] = v.x; sp[1] = v.y; sp[2] = v.z; sp[3] = v.w;
        }
        __syncthreads();
#pragma unroll
        for (int k = 0; k < 32; k++) {
            float x0 = sX[(ng * 2 + 0) * 33 + k];
            float x1 = sX[(ng * 2 + 1) * 33 + k];
            u64 xp0 = pk2(x0, x0);
            u64 xp1 = pk2(x1, x1);
            const u64* wp = (const u64*)&sW[k * 4 + jg * 2];   // 4 col-pairs
            u64 w0 = wp[0], w1 = wp[1], w2 = wp[2], w3 = wp[3];
            fma2(acc[0][0], xp0, w0); fma2(acc[0][1], xp0, w1);
            fma2(acc[0][2], xp0, w2); fma2(acc[0][3], xp0, w3);
            fma2(acc[1][0], xp1, w0); fma2(acc[1][1], xp1, w1);
            fma2(acc[1][2], xp1, w2); fma2(acc[1][3], xp1, w3);
        }
    }
#pragma unroll
    for (int p = 0; p < 2; p++) {
        int node = n0 + ng * 2 + p;
        if (node < n) {
            float l0, h0, l1, h1, l2, h2, l3, h3;
            upk2(l0, h0, acc[p][0]);
            upk2(l1, h1, acc[p][1]);
            upk2(l2, h2, acc[p][2]);
            upk2(l3, h3, acc[p][3]);
            float* op = g_h1 + (size_t)node * HD + jg * 8;
            *(float4*)(op)     = make_float4(l0, h0, l1, h1);
            *(float4*)(op + 4) = make_float4(l2, h2, l3, h3);
        }
    }
}

// ---------------- degree count: 4 edges/thread for MLP ----------------

__global__ void k_cnt(const int* __restrict__ dst, int e) {
    int i = (blockIdx.x * blockDim.x + threadIdx.x) * 4;
    if (i + 3 < e) {
        int d0 = dst[i], d1 = dst[i + 1], d2 = dst[i + 2], d3 = dst[i + 3];
        atomicAdd(&g_cnt[d0], 1);
        atomicAdd(&g_cnt[d1], 1);
        atomicAdd(&g_cnt[d2], 1);
        atomicAdd(&g_cnt[d3], 1);
    } else {
        for (; i < e; i++) atomicAdd(&g_cnt[dst[i]], 1);
    }
}

// ---------------- 3-kernel scan (no co-residency requirement) ----------------

__global__ __launch_bounds__(TPB) void k_scan1(int n) {
    __shared__ int s[256];
    const int t = threadIdx.x;
    const int b = blockIdx.x;
    int base = b * 1024 + t * 4;
    int v0 = (base + 0 < n) ? g_cnt[base + 0] : 0;
    int v1 = (base + 1 < n) ? g_cnt[base + 1] : 0;
    int v2 = (base + 2 < n) ? g_cnt[base + 2] : 0;
    int v3 = (base + 3 < n) ? g_cnt[base + 3] : 0;
    if (base + 0 < n) g_dinv[base + 0] = rsqrtf((float)(v0 + 1));
    if (base + 1 < n) g_dinv[base + 1] = rsqrtf((float)(v1 + 1));
    if (base + 2 < n) g_dinv[base + 2] = rsqrtf((float)(v2 + 1));
    if (base + 3 < n) g_dinv[base + 3] = rsqrtf((float)(v3 + 1));
    int ts = v0 + v1 + v2 + v3;
    s[t] = ts;
    __syncthreads();
#pragma unroll
    for (int off = 1; off < 256; off <<= 1) {
        int xv = (t >= off) ? s[t - off] : 0;
        __syncthreads();
        s[t] += xv;
        __syncthreads();
    }
    int r = s[t] - ts;
    if (t == 255) g_bsum[b] = s[255];
    if (base + 0 < n) { g_rows[base + 0] = r; r += v0; }
    if (base + 1 < n) { g_rows[base + 1] = r; r += v1; }
    if (base + 2 < n) { g_rows[base + 2] = r; r += v2; }
    if (base + 3 < n) { g_rows[base + 3] = r; }
}

__global__ void k_scan2(int nb) {   // one block; nb <= 128
    __shared__ int s[128];
    int t = threadIdx.x;
    int v = (t < nb) ? g_bsum[t] : 0;
    s[t] = v;
    __syncthreads();
#pragma unroll
    for (int off = 1; off < 128; off <<= 1) {
        int xv = (t >= off) ? s[t - off] : 0;
        __syncthreads();
        s[t] += xv;
        __syncthreads();
    }
    if (t < nb) g_bsum[t] = s[t] - v;   // exclusive
}

__global__ void k_scan3(int n, int e) {
    int i = blockIdx.x * blockDim.x + threadIdx.x;
    if (i < n) {
        int r = g_rows[i] + g_bsum[i >> 10];
        g_rows[i] = r;
        g_cur[i]  = r;
        g_cnt[i]  = 0;          // replay-deterministic reset
    }
    if (i == 0) g_rows[n] = e;
}

// ---------------- CSR fill: writes {src, dinv[src]} ----------------

__global__ void k_fill(const int* __restrict__ src, const int* __restrict__ dst, int e) {
    int i = (blockIdx.x * blockDim.x + threadIdx.x) * 4;
    if (i + 3 < e) {
        int s0 = src[i], s1 = src[i + 1], s2 = src[i + 2], s3 = src[i + 3];
        int d0 = dst[i], d1 = dst[i + 1], d2 = dst[i + 2], d3 = dst[i + 3];
        float m0 = g_dinv[s0], m1 = g_dinv[s1], m2 = g_dinv[s2], m3 = g_dinv[s3];
        int p0 = atomicAdd(&g_cur[d0], 1);
        int p1 = atomicAdd(&g_cur[d1], 1);
        int p2 = atomicAdd(&g_cur[d2], 1);
        int p3 = atomicAdd(&g_cur[d3], 1);
        g_edge[p0] = make_int2(s0, __float_as_int(m0));
        g_edge[p1] = make_int2(s1, __float_as_int(m1));
        g_edge[p2] = make_int2(s2, __float_as_int(m2));
        g_edge[p3] = make_int2(s3, __float_as_int(m3));
    } else {
        for (; i < e; i++) {
            int s = src[i];
            int pos = atomicAdd(&g_cur[dst[i]], 1);
            g_edge[pos] = make_int2(s, __float_as_int(g_dinv[s]));
        }
    }
}

// ---------------- fused aggregation: agg1+l2 -> barrier -> agg2+softmax ------
// Grid MUST be fully resident: 592 = 148 x 4 (launch_bounds(256,4)); runs alone
// after the join, so co-residency holds and the spin barrier cannot deadlock.

__global__ __launch_bounds__(TPB, 4) void k_agg(const float* __restrict__ b1,
                                                const float* __restrict__ W2,
                                                const float* __restrict__ b2,
                                                float* __restrict__ out, int n) {
    __shared__ float sW2[HD * 8];
    __shared__ float sb1[HD];
    __shared__ float sb2[8];
    const int t = threadIdx.x;
    const int G = gridDim.x;
    if (t < HD * 8) {
        int j = t >> 3, cc = t & 7;
        sW2[t] = (cc < CD) ? W2[j * CD + cc] : 0.f;
    } else if (t < HD * 8 + HD) {
        sb1[t - HD * 8] = b1[t - HD * 8];
    } else if (t < HD * 8 + HD + 8) {
        int cc = t - HD * 8 - HD;
        sb2[cc] = (cc < CD) ? b2[cc] : -1e30f;
    }
    __syncthreads();

    // ===== phase 1: agg layer 1 + layer-2 transform =====
    {
        const int nG1 = (n + 63) / 64;
        int c = t & 3;
        for (int g = blockIdx.x; g < nG1; g += G) {
            int node = g * 64 + (t >> 2);
            bool valid = node < n;
            if (!valid) node = n - 1;

            float dv = g_dinv[node];
            float4 h = *(const float4*)(g_h1 + (size_t)node * HD + c * 4);
            float4 acc = make_float4(h.x * dv, h.y * dv, h.z * dv, h.w * dv);

            int st = g_rows[node];
            int cnt = g_rows[node + 1] - st;
            int j = 0;
            for (; j + 1 < cnt; j += 2) {
                int2 e0 = g_edge[st + j], e1 = g_edge[st + j + 1];
                float m0 = __int_as_float(e0.y), m1 = __int_as_float(e1.y);
                float4 w0 = *(const float4*)(g_h1 + (size_t)e0.x * HD + c * 4);
                float4 w1 = *(const float4*)(g_h1 + (size_t)e1.x * HD + c * 4);
                acc.x += w0.x * m0 + w1.x * m1;
                acc.y += w0.y * m0 + w1.y * m1;
                acc.z += w0.z * m0 + w1.z * m1;
                acc.w += w0.w * m0 + w1.w * m1;
            }
            if (j < cnt) {
                int2 e0 = g_edge[st + j];
                float m0 = __int_as_float(e0.y);
                float4 w0 = *(const float4*)(g_h1 + (size_t)e0.x * HD + c * 4);
                acc.x += w0.x * m0; acc.y += w0.y * m0;
                acc.z += w0.z * m0; acc.w += w0.w * m0;
            }

            float q0 = fmaxf(acc.x * dv + sb1[c * 4 + 0], 0.f);
            float q1 = fmaxf(acc.y * dv + sb1[c * 4 + 1], 0.f);
            float q2 = fmaxf(acc.z * dv + sb1[c * 4 + 2], 0.f);
            float q3 = fmaxf(acc.w * dv + sb1[c * 4 + 3], 0.f);

            float p[8];
#pragma unroll
            for (int cc = 0; cc < 8; cc++) {
                p[cc] = q0 * sW2[(c * 4 + 0) * 8 + cc]
                      + q1 * sW2[(c * 4 + 1) * 8 + cc]
                      + q2 * sW2[(c * 4 + 2) * 8 + cc]
                      + q3 * sW2[(c * 4 + 3) * 8 + cc];
            }
#pragma unroll
            for (int cc = 0; cc < 8; cc++) {
                p[cc] += __shfl_xor_sync(0xFFFFFFFFu, p[cc], 1);
                p[cc] += __shfl_xor_sync(0xFFFFFFFFu, p[cc], 2);
            }
            if (valid) {
                if (c == 0)
                    *(float4*)(g_h2 + (size_t)node * 8)     = make_float4(p[0], p[1], p[2], p[3]);
                else if (c == 1)
                    *(float4*)(g_h2 + (size_t)node * 8 + 4) = make_float4(p[4], p[5], p[6], 0.f);
            }
        }
    }

    // ===== grid barrier (all blocks resident; self-resetting) =====
    __syncthreads();
    if (t == 0) {
        __threadfence();
        if (atomicAdd(&g_abar, 1) == G - 1) {
            g_abar = 0;
            __threadfence();
            g_aflag = 1;
        } else {
            while (g_aflag == 0) { __nanosleep(64); }
            __threadfence();
        }
    }
    __syncthreads();

    // ===== phase 2: agg layer 2 + bias + log_softmax =====
    {
        const int nG2 = (n + 127) / 128;
        int c = t & 1;
        for (int g = blockIdx.x; g < nG2; g += G) {
            int node = g * 128 + (t >> 1);
            bool valid = node < n;
            if (!valid) node = n - 1;

            float dv = g_dinv[node];
            float4 h = *(const float4*)(g_h2 + (size_t)node * 8 + c * 4);
            float4 acc = make_float4(h.x * dv, h.y * dv, h.z * dv, h.w * dv);

            int st = g_rows[node];
            int cnt = g_rows[node + 1] - st;
            int j = 0;
            for (; j + 1 < cnt; j += 2) {
                int2 e0 = g_edge[st + j], e1 = g_edge[st + j + 1];
                float m0 = __int_as_float(e0.y), m1 = __int_as_float(e1.y);
                float4 w0 = *(const float4*)(g_h2 + (size_t)e0.x * 8 + c * 4);
                float4 w1 = *(const float4*)(g_h2 + (size_t)e1.x * 8 + c * 4);
                acc.x += w0.x * m0 + w1.x * m1;
                acc.y += w0.y * m0 + w1.y * m1;
                acc.z += w0.z * m0 + w1.z * m1;
                acc.w += w0.w * m0 + w1.w * m1;
            }
            if (j < cnt) {
                int2 e0 = g_edge[st + j];
                float m0 = __int_as_float(e0.y);
                float4 w0 = *(const float4*)(g_h2 + (size_t)e0.x * 8 + c * 4);
                acc.x += w0.x * m0; acc.y += w0.y * m0;
                acc.z += w0.z * m0; acc.w += w0.w * m0;
            }

            float o0 = acc.x * dv + sb2[c * 4 + 0];
            float o1 = acc.y * dv + sb2[c * 4 + 1];
            float o2 = acc.z * dv + sb2[c * 4 + 2];
            float o3 = acc.w * dv + sb2[c * 4 + 3];

            float m = fmaxf(fmaxf(o0, o1), fmaxf(o2, o3));
            m = fmaxf(m, __shfl_xor_sync(0xFFFFFFFFu, m, 1));
            float s = expf(o0 - m) + expf(o1 - m) + expf(o2 - m) + expf(o3 - m);
            s += __shfl_xor_sync(0xFFFFFFFFu, s, 1);
            float l = m + logf(s);

            if (valid) {
                float* op = out + (size_t)node * CD + c * 4;
                op[0] = o0 - l; op[1] = o1 - l; op[2] = o2 - l;
                if (c == 0) op[3] = o3 - l;
            }
        }
    }

    // self-reset barrier flag for the next graph replay
    __syncthreads();
    if (t == 0) {
        if (atomicAdd(&g_adone, 1) == G - 1) {
            g_aflag = 0;
            g_adone = 0;
        }
    }
}

// ---------------- launch: GEMM on main stream || CSR chain on side stream ----

extern "C" void kernel_launch(void* const* d_in, const int* in_sizes, int n_in,
                              void* d_out, int out_size) {
    const float* x  = (const float*)d_in[0];
    const int*   ei = (const int*)  d_in[1];
    const float* W1 = (const float*)d_in[2];
    const float* b1 = (const float*)d_in[3];
    const float* W2 = (const float*)d_in[4];
    const float* b2 = (const float*)d_in[5];

    const int n = in_sizes[0] / FIN;
    const int e = in_sizes[1] / 2;
    const int* src = ei;
    const int* dst = ei + e;

    const int nbScan = (n + 1023) / 1024;  // 98
    const int nbE4   = (e / 4 + TPB - 1) / TPB + 1;

    // fork: side stream builds the CSR while main stream runs the GEMM
    cudaEventRecord(g_evFork, 0);
    cudaStreamWaitEvent(g_sideStream, g_evFork, 0);

    k_cnt   <<<nbE4, TPB, 0, g_sideStream>>>(dst, e);
    k_scan1 <<<nbScan, TPB, 0, g_sideStream>>>(n);
    k_scan2 <<<1, 128, 0, g_sideStream>>>(nbScan);
    k_scan3 <<<(n + TPB - 1) / TPB, TPB, 0, g_sideStream>>>(n, e);
    k_fill  <<<nbE4, TPB, 0, g_sideStream>>>(src, dst, e);
    cudaEventRecord(g_evJoin, g_sideStream);

    k_gemm1 <<<(n + 255) / 256, TPB>>>(x, W1, n);

    // join: aggregation needs both h1 (main) and the CSR (side)
    cudaStreamWaitEvent(0, g_evJoin, 0);
    k_agg   <<<592, TPB>>>(b1, W2, b2, (float*)d_out, n);
}

// round 15
// speedup vs baseline: 1.1394x; 1.1394x over previous
#include <cuda_runtime.h>
#include <cuda_fp16.h>
#include <math.h>

#define FIN 512
#define HD  16
#define CD  7
#define NMAX 100000
#define EMAX 3200000
#define TPB  256

// ---------------- scratch (static device globals) ----------------
__device__ int    g_cnt [NMAX];        // in-degree (w/o self-loop); re-zeroed by scan3
__device__ int    g_rows[NMAX + 1];    // CSR row starts (+ total at [n])
__device__ int    g_cur [NMAX];        // fill cursor
__device__ int    g_bsum[128];         // scan block sums
__device__ float  g_dinv[NMAX];
__device__ int2   g_edge[EMAX];        // CSR: {src, bitcast(dinv[src])}
__device__ __half g_h1h [NMAX * HD];   // h1 in fp16 (32B/row)
__device__ __half g_h2h [NMAX * 8];    // h2 in fp16, 7 classes padded to 8 (16B/row)

// ---------------- side stream / events (created before harness checkpoints) --
static cudaStream_t g_sideStream = 0;
static cudaEvent_t  g_evFork = 0, g_evJoin = 0;
namespace {
struct StreamInit {
    StreamInit() {
        int lo, hi;
        cudaDeviceGetStreamPriorityRange(&lo, &hi);
        cudaStreamCreateWithPriority(&g_sideStream, cudaStreamNonBlocking, hi);
        cudaEventCreateWithFlags(&g_evFork, cudaEventDisableTiming);
        cudaEventCreateWithFlags(&g_evJoin, cudaEventDisableTiming);
    }
};
StreamInit g_streamInit;
}

// unpack 8 fp16 (uint4) -> 8 floats
__device__ __forceinline__ void h2f8(uint4 v, float* f) {
    float2 a = __half22float2(*(__half2*)&v.x);
    float2 b = __half22float2(*(__half2*)&v.y);
    float2 c = __half22float2(*(__half2*)&v.z);
    float2 d = __half22float2(*(__half2*)&v.w);
    f[0] = a.x; f[1] = a.y; f[2] = b.x; f[3] = b.y;
    f[4] = c.x; f[5] = c.y; f[6] = d.x; f[7] = d.y;
}

// ---------------- GEMM1: h1 = x @ W1 (R1 kernel; fp16 store epilogue) --------

__global__ __launch_bounds__(256) void k_gemm1(const float* __restrict__ x,
                                               const float* __restrict__ W1, int n) {
    __shared__ float4 sW[32 * 4];        // 32 k x 16 j
    __shared__ float  sX[256 * 33];      // 256 nodes x 32 k (+1 pad)

    const int t  = threadIdx.x;
    const int n0 = blockIdx.x * 256;
    const int ng = t >> 2;               // 0..63
    const int jg = t & 3;                // 0..3

    float acc[4][4];
#pragma unroll
    for (int a = 0; a < 4; a++)
#pragma unroll
        for (int b = 0; b < 4; b++) acc[a][b] = 0.0f;

    for (int k0 = 0; k0 < FIN; k0 += 32) {
        __syncthreads();
        if (t < 128) {
            sW[t] = *(const float4*)(W1 + (size_t)(k0 + (t >> 2)) * HD + (t & 3) * 4);
        }
#pragma unroll
        for (int i = 0; i < 8; i++) {
            int f    = t + 256 * i;
            int nl   = f >> 3;
            int kq   = f & 7;
            int node = n0 + nl;
            float4 v = make_float4(0.f, 0.f, 0.f, 0.f);
            if (node < n) v = *(const float4*)(x + (size_t)node * FIN + k0 + kq * 4);
            float* sp = &sX[nl * 33 + kq * 4];
            sp[0] = v.x; sp[1] = v.y; sp[2] = v.z; sp[3] = v.w;
        }
        __syncthreads();
#pragma unroll
        for (int k = 0; k < 32; k++) {
            float4 wv = sW[k * 4 + jg];
            float x0 = sX[(ng * 4 + 0) * 33 + k];
            float x1 = sX[(ng * 4 + 1) * 33 + k];
            float x2 = sX[(ng * 4 + 2) * 33 + k];
            float x3 = sX[(ng * 4 + 3) * 33 + k];
            acc[0][0] += x0 * wv.x; acc[0][1] += x0 * wv.y; acc[0][2] += x0 * wv.z; acc[0][3] += x0 * wv.w;
            acc[1][0] += x1 * wv.x; acc[1][1] += x1 * wv.y; acc[1][2] += x1 * wv.z; acc[1][3] += x1 * wv.w;
            acc[2][0] += x2 * wv.x; acc[2][1] += x2 * wv.y; acc[2][2] += x2 * wv.z; acc[2][3] += x2 * wv.w;
            acc[3][0] += x3 * wv.x; acc[3][1] += x3 * wv.y; acc[3][2] += x3 * wv.z; acc[3][3] += x3 * wv.w;
        }
    }
#pragma unroll
    for (int ni = 0; ni < 4; ni++) {
        int node = n0 + ng * 4 + ni;
        if (node < n) {
            __half2 ha = __floats2half2_rn(acc[ni][0], acc[ni][1]);
            __half2 hb = __floats2half2_rn(acc[ni][2], acc[ni][3]);
            uint2 u;
            u.x = *(unsigned*)&ha;
            u.y = *(unsigned*)&hb;
            *(uint2*)(g_h1h + (size_t)node * HD + jg * 4) = u;
        }
    }
}

// ---------------- degree count: 4 edges/thread for MLP ----------------

__global__ void k_cnt(const int* __restrict__ dst, int e) {
    int i = (blockIdx.x * blockDim.x + threadIdx.x) * 4;
    if (i + 3 < e) {
        int d0 = dst[i], d1 = dst[i + 1], d2 = dst[i + 2], d3 = dst[i + 3];
        atomicAdd(&g_cnt[d0], 1);
        atomicAdd(&g_cnt[d1], 1);
        atomicAdd(&g_cnt[d2], 1);
        atomicAdd(&g_cnt[d3], 1);
    } else {
        for (; i < e; i++) atomicAdd(&g_cnt[dst[i]], 1);
    }
}

// ---------------- 3-kernel scan (no co-residency requirement) ----------------

__global__ __launch_bounds__(TPB) void k_scan1(int n) {
    __shared__ int s[256];
    const int t = threadIdx.x;
    const int b = blockIdx.x;
    int base = b * 1024 + t * 4;
    int v0 = (base + 0 < n) ? g_cnt[base + 0] : 0;
    int v1 = (base + 1 < n) ? g_cnt[base + 1] : 0;
    int v2 = (base + 2 < n) ? g_cnt[base + 2] : 0;
    int v3 = (base + 3 < n) ? g_cnt[base + 3] : 0;
    if (base + 0 < n) g_dinv[base + 0] = rsqrtf((float)(v0 + 1));
    if (base + 1 < n) g_dinv[base + 1] = rsqrtf((float)(v1 + 1));
    if (base + 2 < n) g_dinv[base + 2] = rsqrtf((float)(v2 + 1));
    if (base + 3 < n) g_dinv[base + 3] = rsqrtf((float)(v3 + 1));
    int ts = v0 + v1 + v2 + v3;
    s[t] = ts;
    __syncthreads();
#pragma unroll
    for (int off = 1; off < 256; off <<= 1) {
        int xv = (t >= off) ? s[t - off] : 0;
        __syncthreads();
        s[t] += xv;
        __syncthreads();
    }
    int r = s[t] - ts;
    if (t == 255) g_bsum[b] = s[255];
    if (base + 0 < n) { g_rows[base + 0] = r; r += v0; }
    if (base + 1 < n) { g_rows[base + 1] = r; r += v1; }
    if (base + 2 < n) { g_rows[base + 2] = r; r += v2; }
    if (base + 3 < n) { g_rows[base + 3] = r; }
}

__global__ void k_scan2(int nb) {   // one block; nb <= 128
    __shared__ int s[128];
    int t = threadIdx.x;
    int v = (t < nb) ? g_bsum[t] : 0;
    s[t] = v;
    __syncthreads();
#pragma unroll
    for (int off = 1; off < 128; off <<= 1) {
        int xv = (t >= off) ? s[t - off] : 0;
        __syncthreads();
        s[t] += xv;
        __syncthreads();
    }
    if (t < nb) g_bsum[t] = s[t] - v;   // exclusive
}

__global__ void k_scan3(int n, int e) {
    int i = blockIdx.x * blockDim.x + threadIdx.x;
    if (i < n) {
        int r = g_rows[i] + g_bsum[i >> 10];
        g_rows[i] = r;
        g_cur[i]  = r;
        g_cnt[i]  = 0;          // replay-deterministic reset
    }
    if (i == 0) g_rows[n] = e;
}

// ---------------- CSR fill: writes {src, dinv[src]} ----------------

__global__ void k_fill(const int* __restrict__ src, const int* __restrict__ dst, int e) {
    int i = (blockIdx.x * blockDim.x + threadIdx.x) * 4;
    if (i + 3 < e) {
        int s0 = src[i], s1 = src[i + 1], s2 = src[i + 2], s3 = src[i + 3];
        int d0 = dst[i], d1 = dst[i + 1], d2 = dst[i + 2], d3 = dst[i + 3];
        float m0 = g_dinv[s0], m1 = g_dinv[s1], m2 = g_dinv[s2], m3 = g_dinv[s3];
        int p0 = atomicAdd(&g_cur[d0], 1);
        int p1 = atomicAdd(&g_cur[d1], 1);
        int p2 = atomicAdd(&g_cur[d2], 1);
        int p3 = atomicAdd(&g_cur[d3], 1);
        g_edge[p0] = make_int2(s0, __float_as_int(m0));
        g_edge[p1] = make_int2(s1, __float_as_int(m1));
        g_edge[p2] = make_int2(s2, __float_as_int(m2));
        g_edge[p3] = make_int2(s3, __float_as_int(m3));
    } else {
        for (; i < e; i++) {
            int s = src[i];
            int pos = atomicAdd(&g_cur[dst[i]], 1);
            g_edge[pos] = make_int2(s, __float_as_int(g_dinv[s]));
        }
    }
}

// ---------------- agg layer 1 + fused layer-2 transform (fp16 tables) --------
// 2 lanes per node; lane c owns feats [8c, 8c+8) as ONE uint4 gather per edge.

__global__ __launch_bounds__(TPB) void k_agg1(const float* __restrict__ b1,
                                              const float* __restrict__ W2, int n) {
    __shared__ float sW2[HD * 8];
    __shared__ float sb1[HD];
    int t = threadIdx.x;
    if (t < HD * 8) {
        int j = t >> 3, cc = t & 7;
        sW2[t] = (cc < CD) ? W2[j * CD + cc] : 0.f;
    } else if (t < HD * 8 + HD) {
        sb1[t - HD * 8] = b1[t - HD * 8];
    }
    __syncthreads();

    int node = blockIdx.x * 128 + (t >> 1);
    int c = t & 1;
    bool valid = node < n;
    if (!valid) node = n - 1;

    float dv = g_dinv[node];
    float acc[8];
    {
        uint4 hs = *(const uint4*)(g_h1h + (size_t)node * HD + c * 8);
        float f[8]; h2f8(hs, f);
#pragma unroll
        for (int k = 0; k < 8; k++) acc[k] = f[k] * dv;
    }

    int st = g_rows[node];
    int cnt = g_rows[node + 1] - st;
    int j = 0;
    for (; j + 1 < cnt; j += 2) {
        int2 e0 = g_edge[st + j], e1 = g_edge[st + j + 1];
        float m0 = __int_as_float(e0.y), m1 = __int_as_float(e1.y);
        uint4 v0 = *(const uint4*)(g_h1h + (size_t)e0.x * HD + c * 8);
        uint4 v1 = *(const uint4*)(g_h1h + (size_t)e1.x * HD + c * 8);
        float f0[8], f1[8];
        h2f8(v0, f0); h2f8(v1, f1);
#pragma unroll
        for (int k = 0; k < 8; k++) acc[k] += f0[k] * m0 + f1[k] * m1;
    }
    if (j < cnt) {
        int2 e0 = g_edge[st + j];
        float m0 = __int_as_float(e0.y);
        uint4 v0 = *(const uint4*)(g_h1h + (size_t)e0.x * HD + c * 8);
        float f0[8]; h2f8(v0, f0);
#pragma unroll
        for (int k = 0; k < 8; k++) acc[k] += f0[k] * m0;
    }

    float q[8];
#pragma unroll
    for (int k = 0; k < 8; k++)
        q[k] = fmaxf(acc[k] * dv + sb1[c * 8 + k], 0.f);

    float p[8];
#pragma unroll
    for (int cc = 0; cc < 8; cc++) {
        float s = 0.f;
#pragma unroll
        for (int k = 0; k < 8; k++) s += q[k] * sW2[(c * 8 + k) * 8 + cc];
        p[cc] = s;
    }
#pragma unroll
    for (int cc = 0; cc < 8; cc++)
        p[cc] += __shfl_xor_sync(0xFFFFFFFFu, p[cc], 1);

    if (valid && c == 0) {
        __half2 ha = __floats2half2_rn(p[0], p[1]);
        __half2 hb = __floats2half2_rn(p[2], p[3]);
        __half2 hc = __floats2half2_rn(p[4], p[5]);
        __half2 hd = __floats2half2_rn(p[6], 0.f);   // col7 == 0
        uint4 u;
        u.x = *(unsigned*)&ha; u.y = *(unsigned*)&hb;
        u.z = *(unsigned*)&hc; u.w = *(unsigned*)&hd;
        *(uint4*)(g_h2h + (size_t)node * 8) = u;
    }
}

// ---------------- agg layer 2 + fused bias + log_softmax (fp16 table) --------
// 1 thread per node; whole 8-wide h2 row in a single uint4 gather.

__global__ __launch_bounds__(TPB) void k_agg2(const float* __restrict__ b2,
                                              float* __restrict__ out, int n) {
    __shared__ float sb2[CD];
    int t = threadIdx.x;
    if (t < CD) sb2[t] = b2[t];
    __syncthreads();

    int node = blockIdx.x * TPB + t;
    if (node >= n) return;

    float dv = g_dinv[node];
    float acc[8];
    {
        uint4 hs = *(const uint4*)(g_h2h + (size_t)node * 8);
        float f[8]; h2f8(hs, f);
#pragma unroll
        for (int k = 0; k < 8; k++) acc[k] = f[k] * dv;
    }

    int st = g_rows[node];
    int cnt = g_rows[node + 1] - st;
    int j = 0;
    for (; j + 1 < cnt; j += 2) {
        int2 e0 = g_edge[st + j], e1 = g_edge[st + j + 1];
        float m0 = __int_as_float(e0.y), m1 = __int_as_float(e1.y);
        uint4 v0 = *(const uint4*)(g_h2h + (size_t)e0.x * 8);
        uint4 v1 = *(const uint4*)(g_h2h + (size_t)e1.x * 8);
        float f0[8], f1[8];
        h2f8(v0, f0); h2f8(v1, f1);
#pragma unroll
        for (int k = 0; k < 8; k++) acc[k] += f0[k] * m0 + f1[k] * m1;
    }
    if (j < cnt) {
        int2 e0 = g_edge[st + j];
        float m0 = __int_as_float(e0.y);
        uint4 v0 = *(const uint4*)(g_h2h + (size_t)e0.x * 8);
        float f0[8]; h2f8(v0, f0);
#pragma unroll
        for (int k = 0; k < 8; k++) acc[k] += f0[k] * m0;
    }

    float o[CD];
#pragma unroll
    for (int cc = 0; cc < CD; cc++) o[cc] = acc[cc] * dv + sb2[cc];

    float m = o[0];
#pragma unroll
    for (int cc = 1; cc < CD; cc++) m = fmaxf(m, o[cc]);
    float s = 0.f;
#pragma unroll
    for (int cc = 0; cc < CD; cc++) s += expf(o[cc] - m);
    float l = m + logf(s);

    float* op = out + (size_t)node * CD;
#pragma unroll
    for (int cc = 0; cc < CD; cc++) op[cc] = o[cc] - l;
}

// ---------------- launch: GEMM on main stream || CSR chain on side stream ----

extern "C" void kernel_launch(void* const* d_in, const int* in_sizes, int n_in,
                              void* d_out, int out_size) {
    const float* x  = (const float*)d_in[0];
    const int*   ei = (const int*)  d_in[1];
    const float* W1 = (const float*)d_in[2];
    const float* b1 = (const float*)d_in[3];
    const float* W2 = (const float*)d_in[4];
    const float* b2 = (const float*)d_in[5];

    const int n = in_sizes[0] / FIN;
    const int e = in_sizes[1] / 2;
    const int* src = ei;
    const int* dst = ei + e;

    const int nbScan = (n + 1023) / 1024;  // 98
    const int nbE4   = (e / 4 + TPB - 1) / TPB + 1;

    // fork: side stream builds the CSR while main stream runs the GEMM
    cudaEventRecord(g_evFork, 0);
    cudaStreamWaitEvent(g_sideStream, g_evFork, 0);

    k_cnt   <<<nbE4, TPB, 0, g_sideStream>>>(dst, e);
    k_scan1 <<<nbScan, TPB, 0, g_sideStream>>>(n);
    k_scan2 <<<1, 128, 0, g_sideStream>>>(nbScan);
    k_scan3 <<<(n + TPB - 1) / TPB, TPB, 0, g_sideStream>>>(n, e);
    k_fill  <<<nbE4, TPB, 0, g_sideStream>>>(src, dst, e);
    cudaEventRecord(g_evJoin, g_sideStream);

    k_gemm1 <<<(n + 255) / 256, TPB>>>(x, W1, n);

    // join: aggregation needs both h1 (main) and the CSR (side)
    cudaStreamWaitEvent(0, g_evJoin, 0);
    k_agg1  <<<(n + 127) / 128, TPB>>>(b1, W2, n);
    k_agg2  <<<(n + TPB - 1) / TPB, TPB>>>(b2, (float*)d_out, n);
}

// round 16
// speedup vs baseline: 1.2020x; 1.0550x over previous
#include <cuda_runtime.h>
#include <cuda_fp16.h>
#include <math.h>

#define FIN 512
#define HD  16
#define CD  7
#define NMAX 100000
#define EMAX 3200000
#define TPB  256
#define XST  40     // halfs per node row in gemm smem (20 words: conflict-free ldmatrix)
#define WST  34     // halfs per n row of transposed W tile

// ---------------- scratch (static device globals) ----------------
__device__ int    g_cnt [NMAX];        // in-degree (w/o self-loop); re-zeroed by scan3
__device__ int    g_rows[NMAX + 1];    // CSR row starts (+ total at [n])
__device__ int    g_cur [NMAX];        // fill cursor
__device__ int    g_bsum[128];         // scan block sums
__device__ float  g_dinv[NMAX];
__device__ int2   g_edge[EMAX];        // CSR: {src, bitcast(dinv[src])}
__device__ __half g_h1h [NMAX * HD];   // h1 in fp16 (32B/row)
__device__ __half g_h2h [NMAX * 8];    // h2 in fp16, 7 classes padded to 8 (16B/row)

// ---------------- side stream / events (created before harness checkpoints) --
static cudaStream_t g_sideStream = 0;
static cudaEvent_t  g_evFork = 0, g_evJoin = 0;
namespace {
struct StreamInit {
    StreamInit() {
        int lo, hi;
        cudaDeviceGetStreamPriorityRange(&lo, &hi);
        cudaStreamCreateWithPriority(&g_sideStream, cudaStreamNonBlocking, hi);
        cudaEventCreateWithFlags(&g_evFork, cudaEventDisableTiming);
        cudaEventCreateWithFlags(&g_evJoin, cudaEventDisableTiming);
    }
};
StreamInit g_streamInit;
}

// unpack 8 fp16 (uint4) -> 8 floats
__device__ __forceinline__ void h2f8(uint4 v, float* f) {
    float2 a = __half22float2(*(__half2*)&v.x);
    float2 b = __half22float2(*(__half2*)&v.y);
    float2 c = __half22float2(*(__half2*)&v.z);
    float2 d = __half22float2(*(__half2*)&v.w);
    f[0] = a.x; f[1] = a.y; f[2] = b.x; f[3] = b.y;
    f[4] = c.x; f[5] = c.y; f[6] = d.x; f[7] = d.y;
}

__device__ __forceinline__ unsigned h2bits(__half2 h) { return *(unsigned*)&h; }

// ---------------- GEMM1: h1 = x @ W1 via mma.sync (fp16 in, fp32 acc) --------
// Block: 256 threads = 8 warps; 256-node x 16-col tile; 32-k chunks.
// Warp w owns nodes w*32..w*32+31 (2 m16 groups) x all 16 cols (2 n8 groups).

__global__ __launch_bounds__(256, 4) void k_gemm1(const float* __restrict__ x,
                                                  const float* __restrict__ W1, int n) {
    __shared__ __half sXh[256 * XST];    // node-major x chunk, fp16
    __shared__ __half sWh[16 * WST];     // W chunk transposed: [n][32 k], fp16

    const int t    = threadIdx.x;
    const int n0   = blockIdx.x * 256;
    const int warp = t >> 5;
    const int lane = t & 31;
    const int g    = lane >> 2;          // 0..7
    const int tig  = lane & 3;           // 0..3

    float acc[2][2][4];                  // [mg][jg][frag]
#pragma unroll
    for (int a = 0; a < 2; a++)
#pragma unroll
        for (int b = 0; b < 2; b++)
#pragma unroll
            for (int c = 0; c < 4; c++) acc[a][b][c] = 0.f;

    const unsigned sXbase = (unsigned)__cvta_generic_to_shared(sXh);
    const int lrow = lane & 15;          // ldmatrix row within m16
    const int kadd = (lane >> 4) * 8;    // ldmatrix col-half select

    for (int k0 = 0; k0 < FIN; k0 += 32) {
        __syncthreads();
        // stage x chunk: 256 nodes x 32 k, fp32 -> fp16
#pragma unroll
        for (int i = 0; i < 8; i++) {
            int f  = t + 256 * i;
            int nl = f >> 3;
            int kq = f & 7;
            int node = n0 + nl;
            float4 v = make_float4(0.f, 0.f, 0.f, 0.f);
            if (node < n) v = *(const float4*)(x + (size_t)node * FIN + k0 + kq * 4);
            __half2 ha = __floats2half2_rn(v.x, v.y);
            __half2 hb = __floats2half2_rn(v.z, v.w);
            uint2 u; u.x = h2bits(ha); u.y = h2bits(hb);
            *(uint2*)&sXh[nl * XST + kq * 4] = u;
        }
        // stage W chunk transposed: Wt[n][k] for k in [k0, k0+32)
        {
            int nn = t & 15;
            int kk = t >> 4;             // 0..15 -> k pair 2kk, 2kk+1
            float w0 = W1[(size_t)(k0 + kk * 2)     * HD + nn];
            float w1 = W1[(size_t)(k0 + kk * 2 + 1) * HD + nn];
            *(unsigned*)&sWh[nn * WST + kk * 2] = h2bits(__floats2half2_rn(w0, w1));
        }
        __syncthreads();

#pragma unroll
        for (int ks = 0; ks < 2; ks++) {
            unsigned bf[2][2];
#pragma unroll
            for (int jg = 0; jg < 2; jg++) {
                int nidx = jg * 8 + g;
                bf[jg][0] = *(const unsigned*)&sWh[nidx * WST + ks * 16 + tig * 2];
                bf[jg][1] = *(const unsigned*)&sWh[nidx * WST + ks * 16 + 8 + tig * 2];
            }
#pragma unroll
            for (int mg = 0; mg < 2; mg++) {
                int row = warp * 32 + mg * 16 + lrow;
                unsigned addr = sXbase + (unsigned)((row * XST + ks * 16 + kadd) * 2);
                unsigned a0, a1, a2, a3;
                asm volatile("ldmatrix.sync.aligned.m8n8.x4.shared.b16 {%0,%1,%2,%3}, [%4];"
                             : "=r"(a0), "=r"(a1), "=r"(a2), "=r"(a3) : "r"(addr));
#pragma unroll
                for (int jg = 0; jg < 2; jg++) {
                    asm volatile(
                        "mma.sync.aligned.m16n8k16.row.col.f32.f16.f16.f32 "
                        "{%0,%1,%2,%3}, {%4,%5,%6,%7}, {%8,%9}, {%0,%1,%2,%3};"
                        : "+f"(acc[mg][jg][0]), "+f"(acc[mg][jg][1]),
                          "+f"(acc[mg][jg][2]), "+f"(acc[mg][jg][3])
                        : "r"(a0), "r"(a1), "r"(a2), "r"(a3),
                          "r"(bf[jg][0]), "r"(bf[jg][1]));
                }
            }
        }
    }

    // epilogue: D frag lane l -> rows {g, g+8}, cols {2tig, 2tig+1}; store half2
#pragma unroll
    for (int mg = 0; mg < 2; mg++) {
#pragma unroll
        for (int jg = 0; jg < 2; jg++) {
            int node = n0 + warp * 32 + mg * 16 + g;
            int col  = jg * 8 + tig * 2;
            if (node < n)
                *(unsigned*)&g_h1h[(size_t)node * HD + col] =
                    h2bits(__floats2half2_rn(acc[mg][jg][0], acc[mg][jg][1]));
            if (node + 8 < n)
                *(unsigned*)&g_h1h[(size_t)(node + 8) * HD + col] =
                    h2bits(__floats2half2_rn(acc[mg][jg][2], acc[mg][jg][3]));
        }
    }
}

// ---------------- degree count: 4 edges/thread for MLP ----------------

__global__ void k_cnt(const int* __restrict__ dst, int e) {
    int i = (blockIdx.x * blockDim.x + threadIdx.x) * 4;
    if (i + 3 < e) {
        int d0 = dst[i], d1 = dst[i + 1], d2 = dst[i + 2], d3 = dst[i + 3];
        atomicAdd(&g_cnt[d0], 1);
        atomicAdd(&g_cnt[d1], 1);
        atomicAdd(&g_cnt[d2], 1);
        atomicAdd(&g_cnt[d3], 1);
    } else {
        for (; i < e; i++) atomicAdd(&g_cnt[dst[i]], 1);
    }
}

// ---------------- 3-kernel scan (no co-residency requirement) ----------------

__global__ __launch_bounds__(TPB) void k_scan1(int n) {
    __shared__ int s[256];
    const int t = threadIdx.x;
    const int b = blockIdx.x;
    int base = b * 1024 + t * 4;
    int v0 = (base + 0 < n) ? g_cnt[base + 0] : 0;
    int v1 = (base + 1 < n) ? g_cnt[base + 1] : 0;
    int v2 = (base + 2 < n) ? g_cnt[base + 2] : 0;
    int v3 = (base + 3 < n) ? g_cnt[base + 3] : 0;
    if (base + 0 < n) g_dinv[base + 0] = rsqrtf((float)(v0 + 1));
    if (base + 1 < n) g_dinv[base + 1] = rsqrtf((float)(v1 + 1));
    if (base + 2 < n) g_dinv[base + 2] = rsqrtf((float)(v2 + 1));
    if (base + 3 < n) g_dinv[base + 3] = rsqrtf((float)(v3 + 1));
    int ts = v0 + v1 + v2 + v3;
    s[t] = ts;
    __syncthreads();
#pragma unroll
    for (int off = 1; off < 256; off <<= 1) {
        int xv = (t >= off) ? s[t - off] : 0;
        __syncthreads();
        s[t] += xv;
        __syncthreads();
    }
    int r = s[t] - ts;
    if (t == 255) g_bsum[b] = s[255];
    if (base + 0 < n) { g_rows[base + 0] = r; r += v0; }
    if (base + 1 < n) { g_rows[base + 1] = r; r += v1; }
    if (base + 2 < n) { g_rows[base + 2] = r; r += v2; }
    if (base + 3 < n) { g_rows[base + 3] = r; }
}

__global__ void k_scan2(int nb) {   // one block; nb <= 128
    __shared__ int s[128];
    int t = threadIdx.x;
    int v = (t < nb) ? g_bsum[t] : 0;
    s[t] = v;
    __syncthreads();
#pragma unroll
    for (int off = 1; off < 128; off <<= 1) {
        int xv = (t >= off) ? s[t - off] : 0;
        __syncthreads();
        s[t] += xv;
        __syncthreads();
    }
    if (t < nb) g_bsum[t] = s[t] - v;   // exclusive
}

__global__ void k_scan3(int n, int e) {
    int i = blockIdx.x * blockDim.x + threadIdx.x;
    if (i < n) {
        int r = g_rows[i] + g_bsum[i >> 10];
        g_rows[i] = r;
        g_cur[i]  = r;
        g_cnt[i]  = 0;          // replay-deterministic reset
    }
    if (i == 0) g_rows[n] = e;
}

// ---------------- CSR fill: writes {src, dinv[src]} ----------------

__global__ void k_fill(const int* __restrict__ src, const int* __restrict__ dst, int e) {
    int i = (blockIdx.x * blockDim.x + threadIdx.x) * 4;
    if (i + 3 < e) {
        int s0 = src[i], s1 = src[i + 1], s2 = src[i + 2], s3 = src[i + 3];
        int d0 = dst[i], d1 = dst[i + 1], d2 = dst[i + 2], d3 = dst[i + 3];
        float m0 = g_dinv[s0], m1 = g_dinv[s1], m2 = g_dinv[s2], m3 = g_dinv[s3];
        int p0 = atomicAdd(&g_cur[d0], 1);
        int p1 = atomicAdd(&g_cur[d1], 1);
        int p2 = atomicAdd(&g_cur[d2], 1);
        int p3 = atomicAdd(&g_cur[d3], 1);
        g_edge[p0] = make_int2(s0, __float_as_int(m0));
        g_edge[p1] = make_int2(s1, __float_as_int(m1));
        g_edge[p2] = make_int2(s2, __float_as_int(m2));
        g_edge[p3] = make_int2(s3, __float_as_int(m3));
    } else {
        for (; i < e; i++) {
            int s = src[i];
            int pos = atomicAdd(&g_cur[dst[i]], 1);
            g_edge[pos] = make_int2(s, __float_as_int(g_dinv[s]));
        }
    }
}

// ---------------- agg layer 1 + fused layer-2 transform (fp16 tables) --------
// 2 lanes per node; lane c owns feats [8c, 8c+8) as ONE uint4 gather per edge.

__global__ __launch_bounds__(TPB) void k_agg1(const float* __restrict__ b1,
                                              const float* __restrict__ W2, int n) {
    __shared__ float sW2[HD * 8];
    __shared__ float sb1[HD];
    int t = threadIdx.x;
    if (t < HD * 8) {
        int j = t >> 3, cc = t & 7;
        sW2[t] = (cc < CD) ? W2[j * CD + cc] : 0.f;
    } else if (t < HD * 8 + HD) {
        sb1[t - HD * 8] = b1[t - HD * 8];
    }
    __syncthreads();

    int node = blockIdx.x * 128 + (t >> 1);
    int c = t & 1;
    bool valid = node < n;
    if (!valid) node = n - 1;

    float dv = g_dinv[node];
    float acc[8];
    {
        uint4 hs = *(const uint4*)(g_h1h + (size_t)node * HD + c * 8);
        float f[8]; h2f8(hs, f);
#pragma unroll
        for (int k = 0; k < 8; k++) acc[k] = f[k] * dv;
    }

    int st = g_rows[node];
    int cnt = g_rows[node + 1] - st;
    int j = 0;
    for (; j + 1 < cnt; j += 2) {
        int2 e0 = g_edge[st + j], e1 = g_edge[st + j + 1];
        float m0 = __int_as_float(e0.y), m1 = __int_as_float(e1.y);
        uint4 v0 = *(const uint4*)(g_h1h + (size_t)e0.x * HD + c * 8);
        uint4 v1 = *(const uint4*)(g_h1h + (size_t)e1.x * HD + c * 8);
        float f0[8], f1[8];
        h2f8(v0, f0); h2f8(v1, f1);
#pragma unroll
        for (int k = 0; k < 8; k++) acc[k] += f0[k] * m0 + f1[k] * m1;
    }
    if (j < cnt) {
        int2 e0 = g_edge[st + j];
        float m0 = __int_as_float(e0.y);
        uint4 v0 = *(const uint4*)(g_h1h + (size_t)e0.x * HD + c * 8);
        float f0[8]; h2f8(v0, f0);
#pragma unroll
        for (int k = 0; k < 8; k++) acc[k] += f0[k] * m0;
    }

    float q[8];
#pragma unroll
    for (int k = 0; k < 8; k++)
        q[k] = fmaxf(acc[k] * dv + sb1[c * 8 + k], 0.f);

    float p[8];
#pragma unroll
    for (int cc = 0; cc < 8; cc++) {
        float s = 0.f;
#pragma unroll
        for (int k = 0; k < 8; k++) s += q[k] * sW2[(c * 8 + k) * 8 + cc];
        p[cc] = s;
    }
#pragma unroll
    for (int cc = 0; cc < 8; cc++)
        p[cc] += __shfl_xor_sync(0xFFFFFFFFu, p[cc], 1);

    if (valid && c == 0) {
        __half2 ha = __floats2half2_rn(p[0], p[1]);
        __half2 hb = __floats2half2_rn(p[2], p[3]);
        __half2 hc = __floats2half2_rn(p[4], p[5]);
        __half2 hd = __floats2half2_rn(p[6], 0.f);   // col7 == 0
        uint4 u;
        u.x = h2bits(ha); u.y = h2bits(hb);
        u.z = h2bits(hc); u.w = h2bits(hd);
        *(uint4*)(g_h2h + (size_t)node * 8) = u;
    }
}

// ---------------- agg layer 2 + fused bias + log_softmax (fp16 table) --------
// 1 thread per node; whole 8-wide h2 row in a single uint4 gather.

__global__ __launch_bounds__(TPB) void k_agg2(const float* __restrict__ b2,
                                              float* __restrict__ out, int n) {
    __shared__ float sb2[CD];
    int t = threadIdx.x;
    if (t < CD) sb2[t] = b2[t];
    __syncthreads();

    int node = blockIdx.x * TPB + t;
    if (node >= n) return;

    float dv = g_dinv[node];
    float acc[8];
    {
        uint4 hs = *(const uint4*)(g_h2h + (size_t)node * 8);
        float f[8]; h2f8(hs, f);
#pragma unroll
        for (int k = 0; k < 8; k++) acc[k] = f[k] * dv;
    }

    int st = g_rows[node];
    int cnt = g_rows[node + 1] - st;
    int j = 0;
    for (; j + 1 < cnt; j += 2) {
        int2 e0 = g_edge[st + j], e1 = g_edge[st + j + 1];
        float m0 = __int_as_float(e0.y), m1 = __int_as_float(e1.y);
        uint4 v0 = *(const uint4*)(g_h2h + (size_t)e0.x * 8);
        uint4 v1 = *(const uint4*)(g_h2h + (size_t)e1.x * 8);
        float f0[8], f1[8];
        h2f8(v0, f0); h2f8(v1, f1);
#pragma unroll
        for (int k = 0; k < 8; k++) acc[k] += f0[k] * m0 + f1[k] * m1;
    }
    if (j < cnt) {
        int2 e0 = g_edge[st + j];
        float m0 = __int_as_float(e0.y);
        uint4 v0 = *(const uint4*)(g_h2h + (size_t)e0.x * 8);
        float f0[8]; h2f8(v0, f0);
#pragma unroll
        for (int k = 0; k < 8; k++) acc[k] += f0[k] * m0;
    }

    float o[CD];
#pragma unroll
    for (int cc = 0; cc < CD; cc++) o[cc] = acc[cc] * dv + sb2[cc];

    float m = o[0];
#pragma unroll
    for (int cc = 1; cc < CD; cc++) m = fmaxf(m, o[cc]);
    float s = 0.f;
#pragma unroll
    for (int cc = 0; cc < CD; cc++) s += expf(o[cc] - m);
    float l = m + logf(s);

    float* op = out + (size_t)node * CD;
#pragma unroll
    for (int cc = 0; cc < CD; cc++) op[cc] = o[cc] - l;
}

// ---------------- launch: GEMM on main stream || CSR chain on side stream ----

extern "C" void kernel_launch(void* const* d_in, const int* in_sizes, int n_in,
                              void* d_out, int out_size) {
    const float* x  = (const float*)d_in[0];
    const int*   ei = (const int*)  d_in[1];
    const float* W1 = (const float*)d_in[2];
    const float* b1 = (const float*)d_in[3];
    const float* W2 = (const float*)d_in[4];
    const float* b2 = (const float*)d_in[5];

    const int n = in_sizes[0] / FIN;
    const int e = in_sizes[1] / 2;
    const int* src = ei;
    const int* dst = ei + e;

    const int nbScan = (n + 1023) / 1024;  // 98
    const int nbE4   = (e / 4 + TPB - 1) / TPB + 1;

    // fork: side stream builds the CSR while main stream runs the GEMM
    cudaEventRecord(g_evFork, 0);
    cudaStreamWaitEvent(g_sideStream, g_evFork, 0);

    k_cnt   <<<nbE4, TPB, 0, g_sideStream>>>(dst, e);
    k_scan1 <<<nbScan, TPB, 0, g_sideStream>>>(n);
    k_scan2 <<<1, 128, 0, g_sideStream>>>(nbScan);
    k_scan3 <<<(n + TPB - 1) / TPB, TPB, 0, g_sideStream>>>(n, e);
    k_fill  <<<nbE4, TPB, 0, g_sideStream>>>(src, dst, e);
    cudaEventRecord(g_evJoin, g_sideStream);

    k_gemm1 <<<(n + 255) / 256, TPB>>>(x, W1, n);

    // join: aggregation needs both h1 (main) and the CSR (side)
    cudaStreamWaitEvent(0, g_evJoin, 0);
    k_agg1  <<<(n + 127) / 128, TPB>>>(b1, W2, n);
    k_agg2  <<<(n + TPB - 1) / TPB, TPB>>>(b2, (float*)d_out, n);
}